// round 6
// baseline (speedup 1.0000x reference)
#include <cuda_runtime.h>

#define NVOX  40000
#define BEVH  496
#define BEVW  432
#define NCELL (BEVH*BEVW)      /* 214272 */
#define CAP   32
#define EPSF  1e-5f

typedef unsigned long long ull;

// ---------------- scratch (static device memory) ----------------
__device__ float g_voxelwise[NVOX * 64];
__device__ int   g_cellCount[NCELL];
__device__ int   g_cellMem[NCELL * CAP];
__device__ int   g_workCell[NVOX];
__device__ int   g_workNumv[NVOX];
__device__ int   g_workMem[NVOX * 16];
__device__ int   g_workCount;

// ---------------- f32x2 helpers ----------------
__device__ __forceinline__ ull pk(float x, float y) {
    ull r; asm("mov.b64 %0,{%1,%2};" : "=l"(r) : "f"(x), "f"(y)); return r;
}
__device__ __forceinline__ float hsum(ull v) {
    float a, b; asm("mov.b64 {%0,%1},%2;" : "=f"(a), "=f"(b) : "l"(v)); return a + b;
}
__device__ __forceinline__ ull ffma2(ull a, ull b, ull c) {
    ull d; asm("fma.rn.f32x2 %0,%1,%2,%3;" : "=l"(d) : "l"(a), "l"(b), "l"(c)); return d;
}

__device__ __forceinline__ float mish(float y) {
    float u = __expf(fminf(y, 25.0f));
    float t = 1.0f + u;
    t = t * t;
    return y * __fdividef(t - 1.0f, t + 1.0f);
}

#define GBAR128(id) asm volatile("bar.sync %0, 128;" :: "r"(id) : "memory")

// ---------------- zero kernels ----------------
__global__ void k_zero_out(float4* out, int n4) {
    int i = blockIdx.x * blockDim.x + threadIdx.x;
    int stride = gridDim.x * blockDim.x;
    float4 z = make_float4(0.f, 0.f, 0.f, 0.f);
    for (; i < n4; i += stride) out[i] = z;
}

__global__ void k_zero_meta() {
    int i = blockIdx.x * blockDim.x + threadIdx.x;
    if (i < NCELL) g_cellCount[i] = 0;
    if (i == 0) g_workCount = 0;
}

// ---------------- VFE: 256 threads = 2 groups of 128 (one voxel each) ----------------
// Per group: lower 64 threads = stage3 (W3 row in regs), upper 64 = stage4 (W4 row),
// software-pipelined over 4-point chunks.
#define VFE_COMMON 656
#define VFE_GSZ    4200
#define VFE_SMEM   ((VFE_COMMON + 2 * VFE_GSZ) * 4)

__global__ __launch_bounds__(256, 2) void k_vfe(
    const float* __restrict__ feat, const int* __restrict__ nvox,
    const float* __restrict__ W1, const float* __restrict__ bn1,
    const float* __restrict__ W2, const float* __restrict__ bn2,
    const float* __restrict__ W3, const float* __restrict__ bn3,
    const float* __restrict__ W4, const float* __restrict__ bn4)
{
    extern __shared__ float sm[];
    float* W1s = sm;           // 64
    float* W2s = sm + 64;      // 512
    float* s1s = sm + 576;     // 8
    float* o1s = sm + 584;     // 8
    float* s2s = sm + 592;     // 32
    float* o2s = sm + 624;     // 32

    const int tid = threadIdx.x;
    const int l = tid & 127;   // lane within group
    const int g = tid >> 7;    // group 0..1

    if (tid < 64) W1s[tid] = W1[tid];
    W2s[tid] = W2[tid]; W2s[tid + 256] = W2[tid + 256];
    if (tid < 8) {
        float s = bn1[tid] * rsqrtf(bn1[24 + tid] + EPSF);
        s1s[tid] = s;
        o1s[tid] = bn1[8 + tid] - bn1[16 + tid] * s;
    }
    if (tid < 32) {
        float s = bn2[tid] * rsqrtf(bn2[96 + tid] + EPSF);
        s2s[tid] = s;
        o2s[tid] = bn2[32 + tid] - bn2[64 + tid] * s;
    }

    const bool lower = (l < 64);
    const int ch = lower ? l : (l - 64);
    // this thread's weight row (W3 for lower half, W4 for upper), packed f32x2
    ull wp[32];
    {
        const float* Wrow = (lower ? W3 : W4) + ch * 64;
#pragma unroll
        for (int k = 0; k < 16; k++) {
            ulonglong2 u = ((const ulonglong2*)Wrow)[k];
            wp[2 * k] = u.x; wp[2 * k + 1] = u.y;
        }
    }
    const float* bnp = lower ? bn3 : bn4;
    const float sS = bnp[ch] * rsqrtf(bnp[192 + ch] + EPSF);
    const float oS = bnp[64 + ch] - bnp[128 + ch] * sS;
    __syncthreads();

    float* gb   = sm + VFE_COMMON + g * VFE_GSZ;
    float* fs   = gb;            // 256   [32][8]
    float* p1s  = gb + 256;      // 288   [32][9]
    float* agg1 = gb + 544;      // 8
    float* p2s  = gb + 552;      // 1056  [32][33]
    float* agg2 = gb + 1608;     // 32
    float* x2s  = gb + 1640;     // 2048  [32][64]
    float* x3s  = gb + 3688;     // 512   double-buffered [2][4][64]

    const int t = l & 31, q = (l >> 5) & 3;
    const int bar = g + 1;
    const int vstep = gridDim.x * 2;

    int v = blockIdx.x * 2 + g;
    float2 pf = make_float2(0.f, 0.f);
    if (v < NVOX) pf = ((const float2*)(feat + (size_t)v * 256))[l];

    for (; v < NVOX; v += vstep) {
        ((float2*)fs)[l] = pf;
        const int numv = nvox[v];
        GBAR128(bar);

        // ---- stage 1: 8 -> 8, thread (t,q) computes channels q*2, q*2+1 ----
        {
            const float* fr = fs + t * 8;
            ull f0 = *(const ull*)(fr), f1 = *(const ull*)(fr + 2);
            ull f2 = *(const ull*)(fr + 4), f3 = *(const ull*)(fr + 6);
#pragma unroll
            for (int j = 0; j < 2; j++) {
                int c = q * 2 + j;
                const float* wr = W1s + c * 8;
                ull acc = ffma2(f0, *(const ull*)wr, 0ull);
                acc = ffma2(f1, *(const ull*)(wr + 2), acc);
                acc = ffma2(f2, *(const ull*)(wr + 4), acc);
                acc = ffma2(f3, *(const ull*)(wr + 6), acc);
                p1s[t * 9 + c] = mish(fmaf(hsum(acc), s1s[c], o1s[c]));
            }
        }
        GBAR128(bar);

        // prefetch next voxel's features while stages 2-4 run
        {
            int vn = v + vstep;
            if (vn < NVOX) pf = ((const float2*)(feat + (size_t)vn * 256))[l];
        }

        if (l < 8) {
            float mx = -3.0e38f;
#pragma unroll
            for (int tt = 0; tt < 32; tt++) mx = fmaxf(mx, p1s[tt * 9 + l]);
            agg1[l] = mx;
        }
        GBAR128(bar);

        // ---- stage 2: 16 -> 32, thread (t,q) computes channels q*8 .. q*8+7 ----
        {
            ull xp[8];
#pragma unroll
            for (int i = 0; i < 4; i++) xp[i] = pk(p1s[t * 9 + 2 * i], p1s[t * 9 + 2 * i + 1]);
#pragma unroll
            for (int i = 0; i < 4; i++) xp[4 + i] = *(const ull*)(agg1 + 2 * i);
#pragma unroll
            for (int j = 0; j < 8; j++) {
                int c = q * 8 + j;
                const ull* wr = (const ull*)(W2s + c * 16);
                ull acc = ffma2(xp[0], wr[0], 0ull);
#pragma unroll
                for (int i = 1; i < 8; i++) acc = ffma2(xp[i], wr[i], acc);
                p2s[t * 33 + c] = mish(fmaf(hsum(acc), s2s[c], o2s[c]));
            }
        }
        GBAR128(bar);
        if (l < 32) {
            float mx = -3.0e38f;
#pragma unroll
            for (int tt = 0; tt < 32; tt++) mx = fmaxf(mx, p2s[tt * 33 + l]);
            agg2[l] = mx;
        }
        GBAR128(bar);

        // ---- masked x2 [32][64]: thread handles channel (l&63), 16 rows ----
        {
            int c2 = l & 63, h = l >> 6;
            float base = (c2 >= 32) ? agg2[c2 - 32] : 0.f;
#pragma unroll
            for (int i = 0; i < 16; i++) {
                int rr = h * 16 + i;
                float val = (c2 < 32) ? p2s[rr * 33 + c2] : base;
                x2s[rr * 64 + c2] = (rr < numv) ? val : 0.f;
            }
        }
        GBAR128(bar);

        // ---- pipelined stages 3/4: lower computes x3[chunk it], upper x4[chunk it-1] ----
        const int nch = (numv + 3) >> 2;
        float vmax = (numv == 32) ? -3.0e38f : 0.f;
        for (int it = 0; it <= nch; ++it) {
            if (lower) {
                if (it < nch) {
                    int t0 = it * 4;
                    int nr = numv - t0; if (nr > 4) nr = 4;
                    float* x3b = x3s + (it & 1) * 256;
#pragma unroll
                    for (int j = 0; j < 4; j++) {
                        if (j < nr) {   // uniform branch
                            const ulonglong2* xr = (const ulonglong2*)(x2s + (t0 + j) * 64);
                            ull acc = 0ull;
#pragma unroll
                            for (int k = 0; k < 16; k++) {
                                ulonglong2 u = xr[k];
                                acc = ffma2(u.x, wp[2 * k], acc);
                                acc = ffma2(u.y, wp[2 * k + 1], acc);
                            }
                            x3b[j * 64 + ch] = mish(fmaf(hsum(acc), sS, oS));
                        }
                    }
                }
            } else {
                if (it >= 1) {
                    int t0 = (it - 1) * 4;
                    int nr = numv - t0; if (nr > 4) nr = 4;
                    const float* x3b = x3s + ((it - 1) & 1) * 256;
#pragma unroll
                    for (int j = 0; j < 4; j++) {
                        if (j < nr) {   // uniform branch
                            const ulonglong2* xr = (const ulonglong2*)(x3b + j * 64);
                            ull acc = 0ull;
#pragma unroll
                            for (int k = 0; k < 16; k++) {
                                ulonglong2 u = xr[k];
                                acc = ffma2(u.x, wp[2 * k], acc);
                                acc = ffma2(u.y, wp[2 * k + 1], acc);
                            }
                            float x4 = mish(fmaf(hsum(acc), sS, oS)) + x2s[(t0 + j) * 64 + ch];
                            vmax = fmaxf(vmax, x4);
                        }
                    }
                }
            }
            GBAR128(bar);
        }
        if (!lower) g_voxelwise[(size_t)v * 64 + ch] = vmax;
    }
}

// ---------------- grouping ----------------
__global__ void k_count(const int* __restrict__ coors) {
    int i = blockIdx.x * blockDim.x + threadIdx.x;
    if (i >= NVOX) return;
    int cell = coors[2 * i] * BEVW + coors[2 * i + 1];
    int p = atomicAdd(&g_cellCount[cell], 1);
    if (p < CAP) g_cellMem[cell * CAP + p] = i;
}

__global__ void k_build() {
    int c = blockIdx.x * blockDim.x + threadIdx.x;
    if (c >= NCELL) return;
    int cnt = g_cellCount[c];
    if (cnt == 0) return;
    int m = min(cnt, CAP);
    int buf[CAP];
    for (int j = 0; j < m; j++) buf[j] = g_cellMem[c * CAP + j];
    for (int a = 1; a < m; a++) {
        int key = buf[a];
        int b = a - 1;
        while (b >= 0 && buf[b] > key) { buf[b + 1] = buf[b]; b--; }
        buf[b + 1] = key;
    }
    int w = atomicAdd(&g_workCount, 1);
    g_workCell[w] = c;
    int nv = min(cnt, 16);
    g_workNumv[w] = nv;
    for (int s = 0; s < 16; s++) g_workMem[w * 16 + s] = (s < nv) ? buf[s] : -1;
}

// ---------------- BFE: persistent 128-thread blocks, batch of 4 cells ----------------
#define BFE_SMEM (27136 * 4 + 72 * 4)

__global__ __launch_bounds__(128, 2) void k_bfe(
    float* __restrict__ out,
    const float* __restrict__ W1, const float* __restrict__ bn1,
    const float* __restrict__ W2, const float* __restrict__ bn2,
    const float* __restrict__ W3, const float* __restrict__ bn3)
{
    extern __shared__ float sm[];
    float* W3s  = sm;                 // [128][132]
    float* x0s  = sm + 16896;         // [4][64][18]
    float* ys   = sm + 21504;         // [4][64][18]
    float* x17s = sm + 26112;         // [4][128]
    float* x18s = sm + 26624;         // [4][128]
    int*   memS  = (int*)(sm + 27136); // [4][16]
    int*   cellS = memS + 64;          // [4]
    int*   nvS   = cellS + 4;          // [4]

    const int tid = threadIdx.x;

    for (int i = tid; i < 128 * 128; i += 128)
        W3s[(i >> 7) * 132 + (i & 127)] = W3[i];

    const int g0 = tid >> 4, q0 = tid & 15;
    ull w1a[8], w1b[8];
#pragma unroll
    for (int k = 0; k < 4; k++) {
        ulonglong2 ua = ((const ulonglong2*)(W1 + g0 * 256 + q0 * 16))[k];
        w1a[2 * k] = ua.x; w1a[2 * k + 1] = ua.y;
        ulonglong2 ub = ((const ulonglong2*)(W1 + (g0 + 8) * 256 + q0 * 16))[k];
        w1b[2 * k] = ub.x; w1b[2 * k + 1] = ub.y;
    }
    const float s1a = bn1[g0*64 + q0]      * rsqrtf(bn1[g0*64 + 48 + q0] + EPSF);
    const float o1a = bn1[g0*64 + 16 + q0] - bn1[g0*64 + 32 + q0] * s1a;
    const int gx = g0 + 8;
    const float s1b = bn1[gx*64 + q0]      * rsqrtf(bn1[gx*64 + 48 + q0] + EPSF);
    const float o1b = bn1[gx*64 + 16 + q0] - bn1[gx*64 + 32 + q0] * s1b;

    const int iB = tid >> 5, gB = (tid >> 1) & 15, cB = tid & 1;
    ull w2p[8];
#pragma unroll
    for (int k = 0; k < 4; k++) {
        ulonglong2 u = ((const ulonglong2*)(W2 + gB * 32 + cB * 16))[k];
        w2p[2 * k] = u.x; w2p[2 * k + 1] = u.y;
    }
    const float s2 = bn2[gB*8 + cB]     * rsqrtf(bn2[gB*8 + 6 + cB] + EPSF);
    const float o2 = bn2[gB*8 + 2 + cB] - bn2[gB*8 + 4 + cB] * s2;

    const float s3 = bn3[tid]       * rsqrtf(bn3[384 + tid] + EPSF);
    const float o3 = bn3[128 + tid] - bn3[256 + tid] * s3;
    __syncthreads();

    const int M = g_workCount;
    const int nb = (M + 3) >> 2;
    for (int batch = blockIdx.x; batch < nb; batch += gridDim.x) {
        if (tid < 64) {
            int w = batch * 4 + (tid >> 4);
            memS[tid] = (w < M) ? g_workMem[w * 16 + (tid & 15)] : -1;
        }
        if (tid < 4) {
            int w = batch * 4 + tid;
            cellS[tid] = (w < M) ? g_workCell[w] : -1;
            nvS[tid]   = (w < M) ? g_workNumv[w] : 0;
        }
        __syncthreads();

#pragma unroll
        for (int i = 0; i < 32; i++) {
            int idx = tid + i * 128;
            int c = idx & 63, p = (idx >> 6) & 15, b = idx >> 10;
            int mm = memS[b * 16 + p];
            x0s[b * 1152 + c * 18 + p] = (mm >= 0) ? g_voxelwise[mm * 64 + c] : 0.f;
        }
        __syncthreads();

        // bfe1
#pragma unroll
        for (int b = 0; b < 4; b++) {
            const int nv = nvS[b];
            const float* x0b = x0s + b * 1152;
            float* yb = ys + b * 1152;
#pragma unroll
            for (int i = 0; i < 4; i++) {
                const float* row = x0b + (g0 * 4 + i) * 18;
                ull acc = 0ull;
#pragma unroll
                for (int kk = 0; kk < 8; kk++)
                    acc = ffma2(*(const ull*)(row + 2 * kk), w1a[kk], acc);
                float yv = mish(fmaf(hsum(acc), s1a, o1a));
                yb[(g0 * 4 + i) * 18 + q0] = (q0 < nv) ? yv : 0.f;
            }
#pragma unroll
            for (int i = 0; i < 4; i++) {
                const float* row = x0b + (gx * 4 + i) * 18;
                ull acc = 0ull;
#pragma unroll
                for (int kk = 0; kk < 8; kk++)
                    acc = ffma2(*(const ull*)(row + 2 * kk), w1b[kk], acc);
                float yv = mish(fmaf(hsum(acc), s1b, o1b));
                yb[(gx * 4 + i) * 18 + q0] = (q0 < nv) ? yv : 0.f;
            }
        }
        __syncthreads();

        // bfe2 -> x17 (torch-cat layout)
#pragma unroll
        for (int b = 0; b < 4; b++) {
            const float* row = ys + b * 1152 + (gB * 4 + iB) * 18;
            ull acc = 0ull;
#pragma unroll
            for (int kk = 0; kk < 8; kk++)
                acc = ffma2(*(const ull*)(row + 2 * kk), w2p[kk], acc);
            x17s[b * 128 + tid] = mish(fmaf(hsum(acc), s2, o2));
        }
        __syncthreads();

        const ulonglong2* wr = (const ulonglong2*)(W3s + tid * 132);
        // bfe3 pass 1
        {
            ull acc[4] = {0ull, 0ull, 0ull, 0ull};
#pragma unroll
            for (int kc = 0; kc < 8; kc++) {
                ulonglong2 wa = wr[kc*4], wb = wr[kc*4+1], wc = wr[kc*4+2], wd = wr[kc*4+3];
#pragma unroll
                for (int b = 0; b < 4; b++) {
                    const ulonglong2* xr = (const ulonglong2*)(x17s + b * 128 + kc * 16);
                    ulonglong2 xa = xr[0], xb = xr[1], xc = xr[2], xd = xr[3];
                    acc[b] = ffma2(xa.x, wa.x, acc[b]); acc[b] = ffma2(xa.y, wa.y, acc[b]);
                    acc[b] = ffma2(xb.x, wb.x, acc[b]); acc[b] = ffma2(xb.y, wb.y, acc[b]);
                    acc[b] = ffma2(xc.x, wc.x, acc[b]); acc[b] = ffma2(xc.y, wc.y, acc[b]);
                    acc[b] = ffma2(xd.x, wd.x, acc[b]); acc[b] = ffma2(xd.y, wd.y, acc[b]);
                }
            }
#pragma unroll
            for (int b = 0; b < 4; b++)
                x18s[b * 128 + tid] = mish(fmaf(hsum(acc[b]), s3, o3));
        }
        __syncthreads();

        // bfe3 pass 2 + scattered store
        {
            ull acc[4] = {0ull, 0ull, 0ull, 0ull};
#pragma unroll
            for (int kc = 0; kc < 8; kc++) {
                ulonglong2 wa = wr[kc*4], wb = wr[kc*4+1], wc = wr[kc*4+2], wd = wr[kc*4+3];
#pragma unroll
                for (int b = 0; b < 4; b++) {
                    const ulonglong2* xr = (const ulonglong2*)(x18s + b * 128 + kc * 16);
                    ulonglong2 xa = xr[0], xb = xr[1], xc = xr[2], xd = xr[3];
                    acc[b] = ffma2(xa.x, wa.x, acc[b]); acc[b] = ffma2(xa.y, wa.y, acc[b]);
                    acc[b] = ffma2(xb.x, wb.x, acc[b]); acc[b] = ffma2(xb.y, wb.y, acc[b]);
                    acc[b] = ffma2(xc.x, wc.x, acc[b]); acc[b] = ffma2(xc.y, wc.y, acc[b]);
                    acc[b] = ffma2(xd.x, wd.x, acc[b]); acc[b] = ffma2(xd.y, wd.y, acc[b]);
                }
            }
#pragma unroll
            for (int b = 0; b < 4; b++) {
                int cell = cellS[b];
                if (cell >= 0) {
                    float x19 = mish(fmaf(hsum(acc[b]), s3, o3));
                    int cy = cell / BEVW;
                    int cx = cell - cy * BEVW;
                    out[tid * NCELL + cx * BEVH + cy] = x19;
                }
            }
        }
        __syncthreads();
    }
}

// ---------------- launcher ----------------
extern "C" void kernel_launch(void* const* d_in, const int* in_sizes, int n_in,
                              void* d_out, int out_size) {
    const float* feat   = (const float*)d_in[0];
    const int*   coors  = (const int*)d_in[1];
    const int*   nvox   = (const int*)d_in[2];
    const float* vfe1_W = (const float*)d_in[3];
    const float* vfe1_b = (const float*)d_in[4];
    const float* vfe2_W = (const float*)d_in[5];
    const float* vfe2_b = (const float*)d_in[6];
    const float* vfe3_W = (const float*)d_in[7];
    const float* vfe3_b = (const float*)d_in[8];
    const float* vfe4_W = (const float*)d_in[9];
    const float* vfe4_b = (const float*)d_in[10];
    const float* bfe1_W = (const float*)d_in[11];
    const float* bfe1_b = (const float*)d_in[12];
    const float* bfe2_W = (const float*)d_in[13];
    const float* bfe2_b = (const float*)d_in[14];
    const float* bfe3_W = (const float*)d_in[15];
    const float* bfe3_b = (const float*)d_in[16];
    float* out = (float*)d_out;

    cudaFuncSetAttribute(k_vfe, cudaFuncAttributeMaxDynamicSharedMemorySize, VFE_SMEM);
    cudaFuncSetAttribute(k_bfe, cudaFuncAttributeMaxDynamicSharedMemorySize, BFE_SMEM);

    // Order chosen so launch index 3 (the one ncu captures) is k_vfe.
    k_zero_meta<<<(NCELL + 255) / 256, 256>>>();
    k_count<<<(NVOX + 255) / 256, 256>>>(coors);
    k_build<<<(NCELL + 255) / 256, 256>>>();
    k_vfe<<<296, 256, VFE_SMEM>>>(feat, nvox, vfe1_W, vfe1_b, vfe2_W, vfe2_b,
                                  vfe3_W, vfe3_b, vfe4_W, vfe4_b);
    k_zero_out<<<4096, 256>>>((float4*)d_out, out_size / 4);
    k_bfe<<<296, 128, BFE_SMEM>>>(out, bfe1_W, bfe1_b, bfe2_W, bfe2_b,
                                  bfe3_W, bfe3_b);
}